// round 8
// baseline (speedup 1.0000x reference)
#include <cuda_runtime.h>
#include <cstdint>

// ParallelVarPatchEmbed, persistent-over-batch tf32 mma.sync kernel, 512 threads.
// Grid: 8(rg) x 8(v) x 2(bg) = 128 persistent CTAs. Per CTA:
//   - W[var] (128x256) loaded once -> tf32 -> SMEM (8 swizzled chunk-tiles)
//   - A streamed for 8 batches through a 4-stage cp.async ring (chunk K=32)
//   - 16 warps, warp tile 32x32; loop-invariant swizzle offsets precomputed.

static constexpr int THREADS = 512;

// SMEM floats: bias[128] | A ring 4 x 4096 | B 8 x 4096
static constexpr int BIAS_OFF = 0;
static constexpr int A_OFF    = 128;
static constexpr int B_OFF    = 128 + 4 * 4096;
static constexpr int SMEM_FLOATS = 128 + 12 * 4096;      // 49280
static constexpr int SMEM_BYTES  = SMEM_FLOATS * 4;      // 197120

__device__ __forceinline__ uint32_t smem_u32(const void* p) {
    uint32_t a;
    asm("{ .reg .u64 t; cvta.to.shared.u64 t, %1; cvt.u32.u64 %0, t; }" : "=r"(a) : "l"(p));
    return a;
}
__device__ __forceinline__ void cpasync16(uint32_t dst, const float* src) {
    asm volatile("cp.async.cg.shared.global [%0], [%1], 16;" :: "r"(dst), "l"(src) : "memory");
}
__device__ __forceinline__ void cpcommit() {
    asm volatile("cp.async.commit_group;" ::: "memory");
}
template <int N> __device__ __forceinline__ void cpwait() {
    asm volatile("cp.async.wait_group %0;" :: "n"(N) : "memory");
}
__device__ __forceinline__ uint32_t f2tf32(float f) {
    uint32_t r;
    asm("cvt.rna.tf32.f32 %0, %1;" : "=r"(r) : "f"(f));
    return r;
}
__device__ __forceinline__ float lds_f(uint32_t addr) {
    float v;
    asm volatile("ld.shared.f32 %0, [%1];" : "=f"(v) : "r"(addr));
    return v;
}
__device__ __forceinline__ void mma8(float* c, const uint32_t* a, uint32_t b0, uint32_t b1) {
    asm volatile(
        "mma.sync.aligned.m16n8k8.row.col.f32.tf32.tf32.f32 "
        "{%0,%1,%2,%3}, {%4,%5,%6,%7}, {%8,%9}, {%0,%1,%2,%3};"
        : "+f"(c[0]), "+f"(c[1]), "+f"(c[2]), "+f"(c[3])
        : "r"(a[0]), "r"(a[1]), "r"(a[2]), "r"(a[3]), "r"(b0), "r"(b1));
}
// swizzled float index within a 128x32 tile: word = m*32 + (k ^ ((m&7)*4))
__device__ __forceinline__ int swi(int m, int k) {
    return m * 32 + (k ^ ((m & 7) * 4));
}
// JAX demotes int64->int32 silently; detect layout from first 32 bytes.
__device__ __forceinline__ int get_var(const int* __restrict__ p32, int v) {
    bool is64 = ((p32[1] | p32[3] | p32[5] | p32[7]) == 0);
    return is64 ? p32[2 * v] : p32[v];
}

__global__ __launch_bounds__(THREADS, 1)
void pve_mma_kernel(const float* __restrict__ x,
                    const int* __restrict__ in_vars,
                    const float* __restrict__ w,
                    const float* __restrict__ bias,
                    float* __restrict__ out)
{
    extern __shared__ float smf[];
    const uint32_t sbase = smem_u32(smf);

    const int tid  = threadIdx.x;
    const int wid  = tid >> 5;
    const int lane = tid & 31;
    const int qrow = lane >> 2;     // 0..7
    const int qcol = lane & 3;      // 0..3
    const int m0   = (wid >> 2) * 32;
    const int n0   = (wid & 3) * 32;

    const int rg = blockIdx.x, v = blockIdx.y, bg = blockIdx.z;
    const int var = get_var(in_vars, v);

    const float* wbase = w + (size_t)var * (128 * 256);

    if (tid < 128) smf[BIAS_OFF + tid] = bias[var * 128 + tid];

    // ---- B prologue: load W[var] once, convert to tf32, 8 swizzled chunk-tiles ----
    #pragma unroll
    for (int i = 0; i < 16; i++) {
        int idx = tid + 512 * i;            // 0..8191 float4s
        int e   = idx >> 6;                 // 0..127
        int k4  = idx & 63;
        int ch  = k4 >> 3;                  // k-chunk 0..7
        int kl  = (k4 & 7) * 4;
        float4 vsrc = *reinterpret_cast<const float4*>(wbase + (size_t)e * 256 + k4 * 4);
        uint4 t;
        t.x = f2tf32(vsrc.x); t.y = f2tf32(vsrc.y);
        t.z = f2tf32(vsrc.z); t.w = f2tf32(vsrc.w);
        *reinterpret_cast<uint4*>(smf + B_OFF + ch * 4096 + swi(e, kl)) = t;
    }

    auto xb = [&](int bi) {
        int b = bg * 8 + bi;
        return x + (size_t)(b * 8 + v) * (512 * 512) + (size_t)rg * 64 * 512;
    };

    // Issue A chunk t (t = bi*8 + ch) into ring slot t%4. 2 float4s per thread.
    auto issueA = [&](int t) {
        const int bi = t >> 3, ch = t & 7;
        const float* xbase = xb(bi);
        const uint32_t abase = sbase + (A_OFF + (t & 3) * 4096) * 4;
        #pragma unroll
        for (int i = 0; i < 2; i++) {
            int idx = tid + 512 * i;        // 0..1023 float4s
            int rl = idx >> 7, c4 = idx & 127;
            int pr = rl >> 1, dp = rl & 1;
            int m  = pr * 32 + (c4 >> 2);
            int kl = dp * 16 + (c4 & 3) * 4;
            cpasync16(abase + swi(m, kl) * 4,
                      xbase + (size_t)(pr * 16 + ch * 2 + dp) * 512 + c4 * 4);
        }
        cpcommit();
    };

    // ---- loop-invariant swizzled k-offsets (bytes): koff[ks][j] ----
    // all fragment rows have row&7 == qrow, so XOR term is qrow*4 for every row.
    uint32_t koff[4][2];
    #pragma unroll
    for (int ks = 0; ks < 4; ks++) {
        koff[ks][0] = (uint32_t)(((ks * 8 + qcol)     ^ (qrow * 4)) * 4);
        koff[ks][1] = (uint32_t)(((ks * 8 + qcol + 4) ^ (qrow * 4)) * 4);
    }
    // loop-invariant row base offsets (bytes, relative to tile base)
    const uint32_t arow0 = (uint32_t)(m0 + qrow) * 128;        // mf=0 row
    const uint32_t brow0 = (uint32_t)(n0 + qrow) * 128;        // nf=0 row

    float acc[2][4][4];
    #pragma unroll
    for (int mf = 0; mf < 2; mf++)
        #pragma unroll
        for (int nf = 0; nf < 4; nf++)
            #pragma unroll
            for (int j = 0; j < 4; j++) acc[mf][nf][j] = 0.0f;

    issueA(0); issueA(1); issueA(2);

    #pragma unroll 1
    for (int t = 0; t < 64; t++) {
        if (t < 62)       cpwait<2>();
        else if (t == 62) cpwait<1>();
        else              cpwait<0>();
        __syncthreads();
        if (t + 3 < 64) issueA(t + 3);

        const uint32_t Asb = sbase + (A_OFF + (t & 3) * 4096) * 4;
        const uint32_t Bsb = sbase + (B_OFF + (t & 7) * 4096) * 4;
        const uint32_t aR0 = Asb + arow0;            // rows m0+qrow, +8, +16, +24
        const uint32_t bR0 = Bsb + brow0;            // rows n0+qrow, +8, +16, +24

        #pragma unroll
        for (int ks = 0; ks < 4; ks++) {
            const uint32_t k0 = koff[ks][0], k1 = koff[ks][1];
            uint32_t a[2][4];
            #pragma unroll
            for (int mf = 0; mf < 2; mf++) {
                const uint32_t r0 = aR0 + (uint32_t)(mf * 16) * 128;
                a[mf][0] = f2tf32(lds_f(r0 + k0));
                a[mf][1] = f2tf32(lds_f(r0 + 8 * 128 + k0));
                a[mf][2] = f2tf32(lds_f(r0 + k1));
                a[mf][3] = f2tf32(lds_f(r0 + 8 * 128 + k1));
            }
            #pragma unroll
            for (int nf = 0; nf < 4; nf++) {
                const uint32_t rb = bR0 + (uint32_t)(nf * 8) * 128;
                uint32_t b0 = __float_as_uint(lds_f(rb + k0));
                uint32_t b1 = __float_as_uint(lds_f(rb + k1));
                mma8(acc[0][nf], a[0], b0, b1);
                mma8(acc[1][nf], a[1], b0, b1);
            }
        }

        if ((t & 7) == 7) {
            // ---- epilogue for batch bi = t>>3 ----
            const int b = bg * 8 + (t >> 3);
            float* obase = out + (((size_t)(b * 8 + v) * 1024) + (size_t)rg * 128) * 128;
            const float* bs = smf + BIAS_OFF;
            #pragma unroll
            for (int mf = 0; mf < 2; mf++) {
                const int r = m0 + mf * 16 + qrow;
                #pragma unroll
                for (int nf = 0; nf < 4; nf++) {
                    const int e0 = n0 + nf * 8 + qcol * 2;
                    float2 lo, hi;
                    lo.x = acc[mf][nf][0] + bs[e0];
                    lo.y = acc[mf][nf][1] + bs[e0 + 1];
                    hi.x = acc[mf][nf][2] + bs[e0];
                    hi.y = acc[mf][nf][3] + bs[e0 + 1];
                    *reinterpret_cast<float2*>(obase + (size_t)r * 128 + e0)       = lo;
                    *reinterpret_cast<float2*>(obase + (size_t)(r + 8) * 128 + e0) = hi;
                    acc[mf][nf][0] = 0.0f; acc[mf][nf][1] = 0.0f;
                    acc[mf][nf][2] = 0.0f; acc[mf][nf][3] = 0.0f;
                }
            }
        }
    }
}

extern "C" void kernel_launch(void* const* d_in, const int* in_sizes, int n_in,
                              void* d_out, int out_size)
{
    const float* x       = (const float*)d_in[0];
    const int*   in_vars = (const int*)d_in[1];
    const float* w       = (const float*)d_in[2];
    const float* bias    = (const float*)d_in[3];
    float*       out     = (float*)d_out;

    cudaFuncSetAttribute(pve_mma_kernel,
                         cudaFuncAttributeMaxDynamicSharedMemorySize, SMEM_BYTES);

    dim3 grid(8, 8, 2);    // (row group, V, batch group) -> 128 persistent CTAs
    pve_mma_kernel<<<grid, THREADS, SMEM_BYTES>>>(x, in_vars, w, bias, out);
}

// round 9
// speedup vs baseline: 1.1593x; 1.1593x over previous
#include <cuda_runtime.h>
#include <cstdint>

// ParallelVarPatchEmbed, persistent tf32 mma.sync kernel, 512 threads =
// two independent 8-warp GEMM groups per CTA sharing one resident B.
// Grid: 8(rg) x 8(v) x 2(bg) = 128 persistent CTAs. Per CTA:
//   - W[var] (128x256) loaded once -> tf32 -> SMEM (8 swizzled chunk-tiles)
//   - group g (warps g*8..g*8+7) streams A for batches bg*8+g*4+{0..3}
//     through its own 3-stage cp.async ring, synced by named barrier g+1.
//   - warp tile 32x64 (4x2 per group), loop-invariant swizzle offsets.

static constexpr int THREADS = 512;

// SMEM floats: bias[128] | B 8 x 4096 | A rings 2 x 3 x 4096
static constexpr int BIAS_OFF = 0;
static constexpr int B_OFF    = 128;
static constexpr int A_OFF    = 128 + 8 * 4096;
static constexpr int SMEM_FLOATS = 128 + 14 * 4096;      // 57472
static constexpr int SMEM_BYTES  = SMEM_FLOATS * 4;      // 229888 (<= 227KB cap)

__device__ __forceinline__ uint32_t smem_u32(const void* p) {
    uint32_t a;
    asm("{ .reg .u64 t; cvta.to.shared.u64 t, %1; cvt.u32.u64 %0, t; }" : "=r"(a) : "l"(p));
    return a;
}
__device__ __forceinline__ void cpasync16(uint32_t dst, const float* src) {
    asm volatile("cp.async.cg.shared.global [%0], [%1], 16;" :: "r"(dst), "l"(src) : "memory");
}
__device__ __forceinline__ void cpcommit() {
    asm volatile("cp.async.commit_group;" ::: "memory");
}
template <int N> __device__ __forceinline__ void cpwait() {
    asm volatile("cp.async.wait_group %0;" :: "n"(N) : "memory");
}
__device__ __forceinline__ void barg(int id) {
    asm volatile("bar.sync %0, 256;" :: "r"(id) : "memory");
}
__device__ __forceinline__ uint32_t f2tf32(float f) {
    uint32_t r;
    asm("cvt.rna.tf32.f32 %0, %1;" : "=r"(r) : "f"(f));
    return r;
}
__device__ __forceinline__ float lds_f(uint32_t addr) {
    float v;
    asm volatile("ld.shared.f32 %0, [%1];" : "=f"(v) : "r"(addr));
    return v;
}
__device__ __forceinline__ void mma8(float* c, const uint32_t* a, uint32_t b0, uint32_t b1) {
    asm volatile(
        "mma.sync.aligned.m16n8k8.row.col.f32.tf32.tf32.f32 "
        "{%0,%1,%2,%3}, {%4,%5,%6,%7}, {%8,%9}, {%0,%1,%2,%3};"
        : "+f"(c[0]), "+f"(c[1]), "+f"(c[2]), "+f"(c[3])
        : "r"(a[0]), "r"(a[1]), "r"(a[2]), "r"(a[3]), "r"(b0), "r"(b1));
}
// swizzled float index within a 128x32 tile: word = m*32 + (k ^ ((m&7)*4))
__device__ __forceinline__ int swi(int m, int k) {
    return m * 32 + (k ^ ((m & 7) * 4));
}
// JAX demotes int64->int32 silently; detect layout from first 32 bytes.
__device__ __forceinline__ int get_var(const int* __restrict__ p32, int v) {
    bool is64 = ((p32[1] | p32[3] | p32[5] | p32[7]) == 0);
    return is64 ? p32[2 * v] : p32[v];
}

__global__ __launch_bounds__(THREADS, 1)
void pve_mma_kernel(const float* __restrict__ x,
                    const int* __restrict__ in_vars,
                    const float* __restrict__ w,
                    const float* __restrict__ bias,
                    float* __restrict__ out)
{
    extern __shared__ float smf[];
    const uint32_t sbase = smem_u32(smf);

    const int tid  = threadIdx.x;
    const int wid  = tid >> 5;
    const int lane = tid & 31;
    const int qrow = lane >> 2;     // 0..7
    const int qcol = lane & 3;      // 0..3
    const int g    = wid >> 3;      // group 0/1
    const int gwid = wid & 7;       // warp within group
    const int gtid = tid & 255;     // thread within group
    const int m0   = (gwid >> 1) * 32;
    const int n0   = (gwid & 1) * 64;

    const int rg = blockIdx.x, v = blockIdx.y, bg = blockIdx.z;
    const int var = get_var(in_vars, v);

    const float* wbase = w + (size_t)var * (128 * 256);

    if (tid < 128) smf[BIAS_OFF + tid] = bias[var * 128 + tid];

    // ---- B prologue (all 512 threads): W[var] -> tf32 -> 8 swizzled chunk-tiles ----
    #pragma unroll
    for (int i = 0; i < 16; i++) {
        int idx = tid + 512 * i;            // 0..8191 float4s
        int e   = idx >> 6;                 // 0..127
        int k4  = idx & 63;
        int ch  = k4 >> 3;
        int kl  = (k4 & 7) * 4;
        float4 vsrc = *reinterpret_cast<const float4*>(wbase + (size_t)e * 256 + k4 * 4);
        uint4 t;
        t.x = f2tf32(vsrc.x); t.y = f2tf32(vsrc.y);
        t.z = f2tf32(vsrc.z); t.w = f2tf32(vsrc.w);
        *reinterpret_cast<uint4*>(smf + B_OFF + ch * 4096 + swi(e, kl)) = t;
    }
    __syncthreads();   // B + bias visible to both groups; only barrier shared by groups

    // group-local A stream: batches bg*8 + g*4 + (0..3)
    auto xb = [&](int bi) {
        int b = bg * 8 + g * 4 + bi;
        return x + (size_t)(b * 8 + v) * (512 * 512) + (size_t)rg * 64 * 512;
    };
    const uint32_t aring = A_OFF + g * 3 * 4096;

    // Issue A chunk t (t = bi*8 + ch, 32 total) into this group's ring slot t%3.
    auto issueA = [&](int t) {
        const int bi = t >> 3, ch = t & 7;
        const float* xbase = xb(bi);
        const uint32_t abase = sbase + (aring + (t % 3) * 4096) * 4;
        #pragma unroll
        for (int i = 0; i < 4; i++) {
            int idx = gtid + 256 * i;       // 0..1023 float4s
            int rl = idx >> 7, c4 = idx & 127;
            int pr = rl >> 1, dp = rl & 1;
            int m  = pr * 32 + (c4 >> 2);
            int kl = dp * 16 + (c4 & 3) * 4;
            cpasync16(abase + swi(m, kl) * 4,
                      xbase + (size_t)(pr * 16 + ch * 2 + dp) * 512 + c4 * 4);
        }
        cpcommit();
    };

    // loop-invariant swizzled k-offsets (bytes)
    uint32_t koff[4][2];
    #pragma unroll
    for (int ks = 0; ks < 4; ks++) {
        koff[ks][0] = (uint32_t)(((ks * 8 + qcol)     ^ (qrow * 4)) * 4);
        koff[ks][1] = (uint32_t)(((ks * 8 + qcol + 4) ^ (qrow * 4)) * 4);
    }
    const uint32_t arow0 = (uint32_t)(m0 + qrow) * 128;
    const uint32_t brow0 = (uint32_t)(n0 + qrow) * 128;

    float acc[2][8][4];
    #pragma unroll
    for (int mf = 0; mf < 2; mf++)
        #pragma unroll
        for (int nf = 0; nf < 8; nf++)
            #pragma unroll
            for (int j = 0; j < 4; j++) acc[mf][nf][j] = 0.0f;

    issueA(0); issueA(1);

    #pragma unroll 1
    for (int t = 0; t < 32; t++) {
        if (t < 31) cpwait<1>();
        else        cpwait<0>();
        barg(g + 1);                 // chunk t visible; slot (t+2)%3 fully consumed
        if (t + 2 < 32) issueA(t + 2);

        const uint32_t Asb = sbase + (aring + (t % 3) * 4096) * 4;
        const uint32_t Bsb = sbase + (B_OFF + (t & 7) * 4096) * 4;
        const uint32_t aR0 = Asb + arow0;
        const uint32_t bR0 = Bsb + brow0;

        #pragma unroll
        for (int ks = 0; ks < 4; ks++) {
            const uint32_t k0 = koff[ks][0], k1 = koff[ks][1];
            uint32_t a[2][4];
            #pragma unroll
            for (int mf = 0; mf < 2; mf++) {
                const uint32_t r0 = aR0 + (uint32_t)(mf * 16) * 128;
                a[mf][0] = f2tf32(lds_f(r0 + k0));
                a[mf][1] = f2tf32(lds_f(r0 + 8 * 128 + k0));
                a[mf][2] = f2tf32(lds_f(r0 + k1));
                a[mf][3] = f2tf32(lds_f(r0 + 8 * 128 + k1));
            }
            #pragma unroll
            for (int nf = 0; nf < 8; nf++) {
                const uint32_t rb = bR0 + (uint32_t)(nf * 8) * 128;
                uint32_t b0 = __float_as_uint(lds_f(rb + k0));
                uint32_t b1 = __float_as_uint(lds_f(rb + k1));
                mma8(acc[0][nf], a[0], b0, b1);
                mma8(acc[1][nf], a[1], b0, b1);
            }
        }

        if ((t & 7) == 7) {
            // ---- epilogue for batch b = bg*8 + g*4 + (t>>3) ----
            const int b = bg * 8 + g * 4 + (t >> 3);
            float* obase = out + (((size_t)(b * 8 + v) * 1024) + (size_t)rg * 128) * 128;
            const float* bs = smf + BIAS_OFF;
            #pragma unroll
            for (int mf = 0; mf < 2; mf++) {
                const int r = m0 + mf * 16 + qrow;
                #pragma unroll
                for (int nf = 0; nf < 8; nf++) {
                    const int e0 = n0 + nf * 8 + qcol * 2;
                    float2 lo, hi;
                    lo.x = acc[mf][nf][0] + bs[e0];
                    lo.y = acc[mf][nf][1] + bs[e0 + 1];
                    hi.x = acc[mf][nf][2] + bs[e0];
                    hi.y = acc[mf][nf][3] + bs[e0 + 1];
                    *reinterpret_cast<float2*>(obase + (size_t)r * 128 + e0)       = lo;
                    *reinterpret_cast<float2*>(obase + (size_t)(r + 8) * 128 + e0) = hi;
                    acc[mf][nf][0] = 0.0f; acc[mf][nf][1] = 0.0f;
                    acc[mf][nf][2] = 0.0f; acc[mf][nf][3] = 0.0f;
                }
            }
        }
    }
}

extern "C" void kernel_launch(void* const* d_in, const int* in_sizes, int n_in,
                              void* d_out, int out_size)
{
    const float* x       = (const float*)d_in[0];
    const int*   in_vars = (const int*)d_in[1];
    const float* w       = (const float*)d_in[2];
    const float* bias    = (const float*)d_in[3];
    float*       out     = (float*)d_out;

    cudaFuncSetAttribute(pve_mma_kernel,
                         cudaFuncAttributeMaxDynamicSharedMemorySize, SMEM_BYTES);

    dim3 grid(8, 8, 2);    // (row group, V, batch group) -> 128 persistent CTAs
    pve_mma_kernel<<<grid, THREADS, SMEM_BYTES>>>(x, in_vars, w, bias, out);
}

// round 10
// speedup vs baseline: 1.2239x; 1.0557x over previous
#include <cuda_runtime.h>
#include <cstdint>

// ParallelVarPatchEmbed, persistent tf32 mma.sync kernel, 512 threads =
// two independent 8-warp GEMM groups per CTA sharing one resident B.
// R10: B stored flat [128][264] (pad-8) with paired-k permutation so each
// fragment (b0,b1) is a single conflict-free ld.shared.v2.f32; no B swizzle math.
// A: swizzled cp.async ring, 2 stages per group.

static constexpr int THREADS = 512;

static constexpr int BROW   = 264;                     // floats per B row (pad 8)
static constexpr int BIAS_OFF = 0;
static constexpr int B_OFF    = 128;
static constexpr int A_OFF    = 128 + 128 * BROW;      // 33920
static constexpr int SMEM_FLOATS = A_OFF + 4 * 4096;   // 50304
static constexpr int SMEM_BYTES  = SMEM_FLOATS * 4;    // 201216

__device__ __forceinline__ uint32_t smem_u32(const void* p) {
    uint32_t a;
    asm("{ .reg .u64 t; cvta.to.shared.u64 t, %1; cvt.u32.u64 %0, t; }" : "=r"(a) : "l"(p));
    return a;
}
__device__ __forceinline__ void cpasync16(uint32_t dst, const float* src) {
    asm volatile("cp.async.cg.shared.global [%0], [%1], 16;" :: "r"(dst), "l"(src) : "memory");
}
__device__ __forceinline__ void cpcommit() {
    asm volatile("cp.async.commit_group;" ::: "memory");
}
template <int N> __device__ __forceinline__ void cpwait() {
    asm volatile("cp.async.wait_group %0;" :: "n"(N) : "memory");
}
__device__ __forceinline__ void barg(int id) {
    asm volatile("bar.sync %0, 256;" :: "r"(id) : "memory");
}
__device__ __forceinline__ uint32_t f2tf32(float f) {
    uint32_t r;
    asm("cvt.rna.tf32.f32 %0, %1;" : "=r"(r) : "f"(f));
    return r;
}
__device__ __forceinline__ float lds_f(uint32_t addr) {
    float v;
    asm volatile("ld.shared.f32 %0, [%1];" : "=f"(v) : "r"(addr));
    return v;
}
__device__ __forceinline__ void lds_v2(uint32_t addr, uint32_t& v0, uint32_t& v1) {
    asm volatile("ld.shared.v2.b32 {%0, %1}, [%2];" : "=r"(v0), "=r"(v1) : "r"(addr));
}
__device__ __forceinline__ void mma8(float* c, const uint32_t* a, uint32_t b0, uint32_t b1) {
    asm volatile(
        "mma.sync.aligned.m16n8k8.row.col.f32.tf32.tf32.f32 "
        "{%0,%1,%2,%3}, {%4,%5,%6,%7}, {%8,%9}, {%0,%1,%2,%3};"
        : "+f"(c[0]), "+f"(c[1]), "+f"(c[2]), "+f"(c[3])
        : "r"(a[0]), "r"(a[1]), "r"(a[2]), "r"(a[3]), "r"(b0), "r"(b1));
}
// A swizzle: word = m*32 + (k ^ ((m&7)*4)) within a 128x32 tile
__device__ __forceinline__ int swi(int m, int k) {
    return m * 32 + (k ^ ((m & 7) * 4));
}
// B paired-k permutation: fragment pair (k, k+4) -> adjacent words
__device__ __forceinline__ int bpos(int k) {
    return (k >> 3) * 8 + (k & 3) * 2 + ((k >> 2) & 1);
}
// JAX demotes int64->int32 silently; detect layout from first 32 bytes.
__device__ __forceinline__ int get_var(const int* __restrict__ p32, int v) {
    bool is64 = ((p32[1] | p32[3] | p32[5] | p32[7]) == 0);
    return is64 ? p32[2 * v] : p32[v];
}

__global__ __launch_bounds__(THREADS, 1)
void pve_mma_kernel(const float* __restrict__ x,
                    const int* __restrict__ in_vars,
                    const float* __restrict__ w,
                    const float* __restrict__ bias,
                    float* __restrict__ out)
{
    extern __shared__ float smf[];
    const uint32_t sbase = smem_u32(smf);

    const int tid  = threadIdx.x;
    const int wid  = tid >> 5;
    const int lane = tid & 31;
    const int qrow = lane >> 2;     // 0..7
    const int qcol = lane & 3;      // 0..3
    const int g    = wid >> 3;      // group 0/1
    const int gwid = wid & 7;
    const int gtid = tid & 255;
    const int m0   = (gwid >> 1) * 32;
    const int n0   = (gwid & 1) * 64;

    const int rg = blockIdx.x, v = blockIdx.y, bg = blockIdx.z;
    const int var = get_var(in_vars, v);

    const float* wbase = w + (size_t)var * (128 * 256);

    if (tid < 128) smf[BIAS_OFF + tid] = bias[var * 128 + tid];

    // ---- B prologue: W[var] -> tf32 -> flat [128][264] paired-k layout ----
    #pragma unroll
    for (int i = 0; i < 16; i++) {
        int idx = tid + 512 * i;            // 0..8191 float4s
        int e   = idx >> 6;                 // 0..127
        int k4  = idx & 63;
        int k   = k4 * 4;                   // 4 consecutive k: same k>>3 group, b2 fixed
        float4 vsrc = *reinterpret_cast<const float4*>(wbase + (size_t)e * 256 + k4 * 4);
        float* row = smf + B_OFF + e * BROW;
        int base = (k >> 3) * 8 + ((k >> 2) & 1);   // + (k&3)*2 per element
        row[base + 0] = __uint_as_float(f2tf32(vsrc.x));
        row[base + 2] = __uint_as_float(f2tf32(vsrc.y));
        row[base + 4] = __uint_as_float(f2tf32(vsrc.z));
        row[base + 6] = __uint_as_float(f2tf32(vsrc.w));
    }
    __syncthreads();   // B + bias visible to both groups

    // group-local A stream: batches bg*8 + g*4 + (0..3)
    auto xb = [&](int bi) {
        int b = bg * 8 + g * 4 + bi;
        return x + (size_t)(b * 8 + v) * (512 * 512) + (size_t)rg * 64 * 512;
    };
    const uint32_t aring = A_OFF + g * 2 * 4096;

    auto issueA = [&](int t) {
        const int bi = t >> 3, ch = t & 7;
        const float* xbase = xb(bi);
        const uint32_t abase = sbase + (aring + (t & 1) * 4096) * 4;
        #pragma unroll
        for (int i = 0; i < 4; i++) {
            int idx = gtid + 256 * i;       // 0..1023 float4s
            int rl = idx >> 7, c4 = idx & 127;
            int pr = rl >> 1, dp = rl & 1;
            int m  = pr * 32 + (c4 >> 2);
            int kl = dp * 16 + (c4 & 3) * 4;
            cpasync16(abase + swi(m, kl) * 4,
                      xbase + (size_t)(pr * 16 + ch * 2 + dp) * 512 + c4 * 4);
        }
        cpcommit();
    };

    // loop-invariant offsets
    uint32_t koff[4][2];                    // A swizzled k offsets (bytes)
    #pragma unroll
    for (int ks = 0; ks < 4; ks++) {
        koff[ks][0] = (uint32_t)(((ks * 8 + qcol)     ^ (qrow * 4)) * 4);
        koff[ks][1] = (uint32_t)(((ks * 8 + qcol + 4) ^ (qrow * 4)) * 4);
    }
    const uint32_t arow0 = (uint32_t)(m0 + qrow) * 128;
    // B fragment base (bytes): row (n0+qrow), + qcol pair offset; per chunk +ch*128, per ks +32
    const uint32_t bfrag0 = (uint32_t)(B_OFF + (n0 + qrow) * BROW + qcol * 2) * 4;

    float acc[2][8][4];
    #pragma unroll
    for (int mf = 0; mf < 2; mf++)
        #pragma unroll
        for (int nf = 0; nf < 8; nf++)
            #pragma unroll
            for (int j = 0; j < 4; j++) acc[mf][nf][j] = 0.0f;

    issueA(0);

    #pragma unroll 1
    for (int t = 0; t < 32; t++) {
        cpwait<0>();
        barg(g + 1);                 // chunk t visible; slot (t+1)&1 fully consumed
        if (t + 1 < 32) issueA(t + 1);

        const uint32_t aR0 = sbase + (aring + (t & 1) * 4096) * 4 + arow0;
        const uint32_t bR0 = sbase + bfrag0 + (uint32_t)(t & 7) * 128;

        #pragma unroll
        for (int ks = 0; ks < 4; ks++) {
            const uint32_t k0 = koff[ks][0], k1 = koff[ks][1];
            uint32_t a[2][4];
            #pragma unroll
            for (int mf = 0; mf < 2; mf++) {
                const uint32_t r0 = aR0 + (uint32_t)(mf * 16) * 128;
                a[mf][0] = f2tf32(lds_f(r0 + k0));
                a[mf][1] = f2tf32(lds_f(r0 + 8 * 128 + k0));
                a[mf][2] = f2tf32(lds_f(r0 + k1));
                a[mf][3] = f2tf32(lds_f(r0 + 8 * 128 + k1));
            }
            const uint32_t bks = bR0 + (uint32_t)(ks * 32);
            #pragma unroll
            for (int nf = 0; nf < 8; nf++) {
                uint32_t b0, b1;
                lds_v2(bks + (uint32_t)(nf * 8) * (BROW * 4), b0, b1);
                mma8(acc[0][nf], a[0], b0, b1);
                mma8(acc[1][nf], a[1], b0, b1);
            }
        }

        if ((t & 7) == 7) {
            const int b = bg * 8 + g * 4 + (t >> 3);
            float* obase = out + (((size_t)(b * 8 + v) * 1024) + (size_t)rg * 128) * 128;
            const float* bs = smf + BIAS_OFF;
            #pragma unroll
            for (int mf = 0; mf < 2; mf++) {
                const int r = m0 + mf * 16 + qrow;
                #pragma unroll
                for (int nf = 0; nf < 8; nf++) {
                    const int e0 = n0 + nf * 8 + qcol * 2;
                    float2 lo, hi;
                    lo.x = acc[mf][nf][0] + bs[e0];
                    lo.y = acc[mf][nf][1] + bs[e0 + 1];
                    hi.x = acc[mf][nf][2] + bs[e0];
                    hi.y = acc[mf][nf][3] + bs[e0 + 1];
                    *reinterpret_cast<float2*>(obase + (size_t)r * 128 + e0)       = lo;
                    *reinterpret_cast<float2*>(obase + (size_t)(r + 8) * 128 + e0) = hi;
                    acc[mf][nf][0] = 0.0f; acc[mf][nf][1] = 0.0f;
                    acc[mf][nf][2] = 0.0f; acc[mf][nf][3] = 0.0f;
                }
            }
        }
    }
}

extern "C" void kernel_launch(void* const* d_in, const int* in_sizes, int n_in,
                              void* d_out, int out_size)
{
    const float* x       = (const float*)d_in[0];
    const int*   in_vars = (const int*)d_in[1];
    const float* w       = (const float*)d_in[2];
    const float* bias    = (const float*)d_in[3];
    float*       out     = (float*)d_out;

    cudaFuncSetAttribute(pve_mma_kernel,
                         cudaFuncAttributeMaxDynamicSharedMemorySize, SMEM_BYTES);

    dim3 grid(8, 8, 2);    // (row group, V, batch group) -> 128 persistent CTAs
    pve_mma_kernel<<<grid, THREADS, SMEM_BYTES>>>(x, in_vars, w, bias, out);
}